// round 13
// baseline (speedup 1.0000x reference)
#include <cuda_runtime.h>
#include <cuda_bf16.h>
#include <math_constants.h>
#include <cstdint>

#define NN 50000
#define EE 1200000
#define DD 128
#define RR 6
#define KK (RR * DD)   // 768
#define NEG_SLOPE 0.2f
#define CAP_ET 48              // per (node, relation) bucket capacity (deg_r ~ Poisson(4))
#define STR6 (RR * CAP_ET)     // 288 slots per node

#define ZB ((NN * RR + 255) / 256)   // 1172 blocks to zero counters

// ---------------- scratch ----------------
__device__ __nv_bfloat16 g_Tb[(size_t)NN * KK];    // bf16 T (76.8 MB)
__device__ __nv_bfloat16 g_wt[(size_t)DD * KK];    // W^T bf16 [128][768]
__device__ __nv_bfloat16 g_xb[(size_t)NN * DD];    // bf16 x copy (12.8 MB)
__device__ int2  g_cse[(size_t)NN * STR6];         // {orig edge id, src} (115.2 MB)
__device__ float g_nqk[NN * 12];
__device__ float g_cq[KK];
__device__ float g_ck[KK];
__device__ int   g_cnt6[NN * RR];                  // per (node, relation) degree

// ---------------- K1: fused setup (zero counters + W^T bf16 + cq/ck) ----------------
__global__ __launch_bounds__(256) void setup_kernel(
    const float* __restrict__ w, const float* __restrict__ q, const float* __restrict__ k)
{
    const int b = blockIdx.x;
    const int t = threadIdx.x;

    if (b < ZB) {
        int i = b * 256 + t;
        if (i < NN * RR) g_cnt6[i] = 0;
        return;
    }
    if (b < ZB + 96) {
        int v = b - ZB;
        int n0 = (v & 3) * 32;        // 4 tiles across DD=128
        int k0 = (v >> 2) * 32;       // 24 tiles across KK=768
        int tx = t & 31, ty = t >> 5; // 32 x 8
        __shared__ float tile[32][33];
#pragma unroll
        for (int i = 0; i < 4; i++)
            tile[ty + i * 8][tx] = w[(size_t)(k0 + ty + i * 8) * DD + n0 + tx];
        __syncthreads();
#pragma unroll
        for (int i = 0; i < 4; i++)
            g_wt[(size_t)(n0 + ty + i * 8) * KK + k0 + tx] =
                __float2bfloat16_rn(tile[tx][ty + i * 8]);
        return;
    }
    {
        int warp = (b - (ZB + 96)) * 8 + (t >> 5);
        int lane = t & 31;
        if (warp >= KK) return;
        const float* row = w + (size_t)warp * DD;
        float sq = 0.f, sk = 0.f;
#pragma unroll
        for (int o = lane; o < DD; o += 32) {
            float v = row[o];
            sq = fmaf(v, q[o], sq);
            sk = fmaf(v, k[o], sk);
        }
#pragma unroll
        for (int off = 16; off > 0; off >>= 1) {
            sq += __shfl_xor_sync(0xffffffffu, sq, off);
            sk += __shfl_xor_sync(0xffffffffu, sk, off);
        }
        if (lane == 0) { g_cq[warp] = sq; g_ck[warp] = sk; }
    }
}

// ---------------- K2: bucket scatter by (dst, relation) ----------------
__global__ void scatter_kernel(const int* __restrict__ ei, const int* __restrict__ etype) {
    int e = blockIdx.x * blockDim.x + threadIdx.x;
    if (e < EE) {
        int dst = ei[EE + e];
        int et  = etype[e];
        int pos = atomicAdd(&g_cnt6[dst * RR + et], 1);
        if (pos < CAP_ET)
            g_cse[(size_t)dst * STR6 + et * CAP_ET + pos] = make_int2(e, ei[e]);
    }
}

// ---------------- K3: nq/nk + bf16 x copy ----------------
__global__ __launch_bounds__(256) void nqnk_kernel(const float* __restrict__ x)
{
    int warp = (blockIdx.x * blockDim.x + threadIdx.x) >> 5;
    int lane = threadIdx.x & 31;
    if (warp >= NN) return;
    const int n = warp;
    const float4 xv = *(const float4*)&x[(size_t)n * DD + lane * 4];

    {
        __nv_bfloat162 lo = __floats2bfloat162_rn(xv.x, xv.y);
        __nv_bfloat162 hi = __floats2bfloat162_rn(xv.z, xv.w);
        *(uint2*)&g_xb[(size_t)n * DD + lane * 4] =
            make_uint2(*(uint32_t*)&lo, *(uint32_t*)&hi);
    }

#pragma unroll
    for (int r = 0; r < RR; r++) {
        const float4 cq = *(const float4*)&g_cq[r * DD + lane * 4];
        const float4 ck = *(const float4*)&g_ck[r * DD + lane * 4];
        float sq = xv.x * cq.x + xv.y * cq.y + xv.z * cq.z + xv.w * cq.w;
        float sk = xv.x * ck.x + xv.y * ck.y + xv.z * ck.z + xv.w * ck.w;
#pragma unroll
        for (int off = 16; off > 0; off >>= 1) {
            sq += __shfl_xor_sync(0xffffffffu, sq, off);
            sk += __shfl_xor_sync(0xffffffffu, sk, off);
        }
        if (lane == 0) {
            g_nqk[n * 12 + r * 2]     = sq;
            g_nqk[n * 12 + r * 2 + 1] = sk;
        }
    }
}

// ---------------- K4: node softmax + per-relation aggregation -> bf16 T ----------------
__device__ __forceinline__ float4 xb_load(int src, int lane) {
    uint2 p = __ldg((const uint2*)&g_xb[(size_t)src * DD + lane * 4]);
    __nv_bfloat162 b0 = *(__nv_bfloat162*)&p.x;
    __nv_bfloat162 b1 = *(__nv_bfloat162*)&p.y;
    float2 f0 = __bfloat1622float2(b0);
    float2 f1 = __bfloat1622float2(b1);
    return make_float4(f0.x, f0.y, f1.x, f1.y);
}

__global__ __launch_bounds__(256) void node_kernel(float* __restrict__ alpha_out)
{
    int warp = (blockIdx.x * blockDim.x + threadIdx.x) >> 5;
    int lane = threadIdx.x & 31;
    if (warp >= NN) return;
    const int n = warp;
    const size_t base = (size_t)n * STR6;

    int degs[RR];
    float nqr[RR];
#pragma unroll
    for (int r = 0; r < RR; r++) {
        int c = g_cnt6[n * RR + r];
        degs[r] = (c < CAP_ET) ? c : CAP_ET;
        nqr[r]  = g_nqk[n * 12 + r * 2];
    }

    bool fast = true;
#pragma unroll
    for (int r = 0; r < RR; r++) fast &= (degs[r] <= 32);

    if (fast) {
        // ---- one edge per lane per relation, all state in registers ----
        float lg[RR];
        int   eid[RR], srcv[RR];
#pragma unroll
        for (int r = 0; r < RR; r++) {
            lg[r] = -CUDART_INF_F; eid[r] = 0; srcv[r] = 0;
            if (lane < degs[r]) {
                int2 c = g_cse[base + r * CAP_ET + lane];
                eid[r]  = c.x;
                srcv[r] = c.y;
                float nk = __ldg(&g_nqk[c.y * 12 + r * 2 + 1]);
                float l = nqr[r] + nk;
                lg[r] = (l > 0.f) ? l : NEG_SLOPE * l;
            }
        }
        float m = lg[0];
#pragma unroll
        for (int r = 1; r < RR; r++) m = fmaxf(m, lg[r]);
#pragma unroll
        for (int o = 16; o > 0; o >>= 1) m = fmaxf(m, __shfl_xor_sync(0xffffffffu, m, o));

        float ev[RR];
        float dsum = 0.f;
#pragma unroll
        for (int r = 0; r < RR; r++) {
            ev[r] = (lane < degs[r]) ? __expf(lg[r] - m) : 0.f;
            dsum += ev[r];
        }
#pragma unroll
        for (int o = 16; o > 0; o >>= 1) dsum += __shfl_xor_sync(0xffffffffu, dsum, o);
        const float invden = 1.f / (dsum + 1e-16f);

#pragma unroll
        for (int r = 0; r < RR; r++)
            if (lane < degs[r]) alpha_out[eid[r]] = ev[r] * invden;

        // per-relation aggregation: single accumulator, no dispatch
#pragma unroll
        for (int r = 0; r < RR; r++) {
            float4 acc = make_float4(0.f, 0.f, 0.f, 0.f);
            int dr = degs[r];
            int rounds = (dr + 3) & ~3;
            for (int t = 0; t < rounds; t += 4) {
                int   s0 = __shfl_sync(0xffffffffu, srcv[r], t);
                int   s1 = __shfl_sync(0xffffffffu, srcv[r], t + 1);
                int   s2 = __shfl_sync(0xffffffffu, srcv[r], t + 2);
                int   s3 = __shfl_sync(0xffffffffu, srcv[r], t + 3);
                float e0 = __shfl_sync(0xffffffffu, ev[r], t);
                float e1 = __shfl_sync(0xffffffffu, ev[r], t + 1);
                float e2 = __shfl_sync(0xffffffffu, ev[r], t + 2);
                float e3 = __shfl_sync(0xffffffffu, ev[r], t + 3);
                float4 x0 = xb_load(s0, lane);
                float4 x1 = xb_load(s1, lane);
                float4 x2 = xb_load(s2, lane);
                float4 x3 = xb_load(s3, lane);
                acc.x = fmaf(e0, x0.x, acc.x); acc.y = fmaf(e0, x0.y, acc.y);
                acc.z = fmaf(e0, x0.z, acc.z); acc.w = fmaf(e0, x0.w, acc.w);
                acc.x = fmaf(e1, x1.x, acc.x); acc.y = fmaf(e1, x1.y, acc.y);
                acc.z = fmaf(e1, x1.z, acc.z); acc.w = fmaf(e1, x1.w, acc.w);
                acc.x = fmaf(e2, x2.x, acc.x); acc.y = fmaf(e2, x2.y, acc.y);
                acc.z = fmaf(e2, x2.z, acc.z); acc.w = fmaf(e2, x2.w, acc.w);
                acc.x = fmaf(e3, x3.x, acc.x); acc.y = fmaf(e3, x3.y, acc.y);
                acc.z = fmaf(e3, x3.z, acc.z); acc.w = fmaf(e3, x3.w, acc.w);
            }
            __nv_bfloat162 lo = __floats2bfloat162_rn(acc.x * invden, acc.y * invden);
            __nv_bfloat162 hi = __floats2bfloat162_rn(acc.z * invden, acc.w * invden);
            *(uint2*)&g_Tb[(size_t)n * KK + r * DD + lane * 4] =
                make_uint2(*(uint32_t*)&lo, *(uint32_t*)&hi);
        }
    } else {
        // ---- rare general path: chunked, recompute logits in pass B ----
        float lm = -CUDART_INF_F, ls = 0.f;
        for (int r = 0; r < RR; r++) {
            for (int j0 = 0; j0 < degs[r]; j0 += 32) {
                int j = j0 + lane;
                if (j < degs[r]) {
                    int2 c = g_cse[base + r * CAP_ET + j];
                    float nk = __ldg(&g_nqk[c.y * 12 + r * 2 + 1]);
                    float l = nqr[r] + nk;
                    l = (l > 0.f) ? l : NEG_SLOPE * l;
                    float nlm = fmaxf(lm, l);
                    ls = ls * __expf(lm - nlm) + __expf(l - nlm);
                    lm = nlm;
                }
            }
        }
        float m = lm;
#pragma unroll
        for (int o = 16; o > 0; o >>= 1) m = fmaxf(m, __shfl_xor_sync(0xffffffffu, m, o));
        float contrib = (ls > 0.f) ? ls * __expf(lm - m) : 0.f;
        float dsum = contrib;
#pragma unroll
        for (int o = 16; o > 0; o >>= 1) dsum += __shfl_xor_sync(0xffffffffu, dsum, o);
        const float invden = 1.f / (dsum + 1e-16f);

        for (int r = 0; r < RR; r++) {
            float4 acc = make_float4(0.f, 0.f, 0.f, 0.f);
            for (int j0 = 0; j0 < degs[r]; j0 += 32) {
                int j = j0 + lane;
                int sv = 0;
                float evv = 0.f;
                if (j < degs[r]) {
                    int2 c = g_cse[base + r * CAP_ET + j];
                    sv = c.y;
                    float nk = __ldg(&g_nqk[c.y * 12 + r * 2 + 1]);
                    float l = nqr[r] + nk;
                    l = (l > 0.f) ? l : NEG_SLOPE * l;
                    evv = __expf(l - m);
                    alpha_out[c.x] = evv * invden;
                }
                int cnt = degs[r] - j0; if (cnt > 32) cnt = 32;
                int rounds = (cnt + 3) & ~3;
                for (int t = 0; t < rounds; t += 4) {
                    int   s0 = __shfl_sync(0xffffffffu, sv, t);
                    int   s1 = __shfl_sync(0xffffffffu, sv, t + 1);
                    int   s2 = __shfl_sync(0xffffffffu, sv, t + 2);
                    int   s3 = __shfl_sync(0xffffffffu, sv, t + 3);
                    float e0 = __shfl_sync(0xffffffffu, evv, t);
                    float e1 = __shfl_sync(0xffffffffu, evv, t + 1);
                    float e2 = __shfl_sync(0xffffffffu, evv, t + 2);
                    float e3 = __shfl_sync(0xffffffffu, evv, t + 3);
                    float4 x0 = xb_load(s0, lane);
                    float4 x1 = xb_load(s1, lane);
                    float4 x2 = xb_load(s2, lane);
                    float4 x3 = xb_load(s3, lane);
                    acc.x = fmaf(e0, x0.x, acc.x); acc.y = fmaf(e0, x0.y, acc.y);
                    acc.z = fmaf(e0, x0.z, acc.z); acc.w = fmaf(e0, x0.w, acc.w);
                    acc.x = fmaf(e1, x1.x, acc.x); acc.y = fmaf(e1, x1.y, acc.y);
                    acc.z = fmaf(e1, x1.z, acc.z); acc.w = fmaf(e1, x1.w, acc.w);
                    acc.x = fmaf(e2, x2.x, acc.x); acc.y = fmaf(e2, x2.y, acc.y);
                    acc.z = fmaf(e2, x2.z, acc.z); acc.w = fmaf(e2, x2.w, acc.w);
                    acc.x = fmaf(e3, x3.x, acc.x); acc.y = fmaf(e3, x3.y, acc.y);
                    acc.z = fmaf(e3, x3.z, acc.z); acc.w = fmaf(e3, x3.w, acc.w);
                }
            }
            __nv_bfloat162 lo = __floats2bfloat162_rn(acc.x * invden, acc.y * invden);
            __nv_bfloat162 hi = __floats2bfloat162_rn(acc.z * invden, acc.w * invden);
            *(uint2*)&g_Tb[(size_t)n * KK + r * DD + lane * 4] =
                make_uint2(*(uint32_t*)&lo, *(uint32_t*)&hi);
        }
    }
}

// ---------------- K5: bf16 tensor-core GEMM with cp.async double buffering ----------------
#define GBM 128
#define GBK 64
#define SSTR 72
#define NIT (KK / GBK)          // 12
#define A_STAGE (GBM * SSTR)
#define B_STAGE (DD * SSTR)
#define SMEM_ELEMS (2 * (A_STAGE + B_STAGE))

__device__ __forceinline__ void cp16(uint32_t saddr, const void* gptr, uint32_t szbytes) {
    asm volatile("cp.async.ca.shared.global [%0], [%1], 16, %2;\n"
                 :: "r"(saddr), "l"(gptr), "r"(szbytes));
}

__global__ __launch_bounds__(256) void gemm_tc_kernel(
    const float* __restrict__ x, const float* __restrict__ bias, float* __restrict__ out)
{
    extern __shared__ __nv_bfloat16 smem[];
    const int m0   = blockIdx.x * GBM;
    const int t    = threadIdx.x;
    const int warp = t >> 5;
    const int lane = t & 31;
    const int g    = lane >> 2;
    const int tig  = lane & 3;
    const int R0   = (warp & 3) * 32;
    const int C0   = (warp >> 2) * 64;

    const uint32_t smem_base = (uint32_t)__cvta_generic_to_shared(smem);

    float acc[2][8][4];
#pragma unroll
    for (int mt = 0; mt < 2; mt++)
#pragma unroll
        for (int nt = 0; nt < 8; nt++)
#pragma unroll
            for (int i = 0; i < 4; i++) acc[mt][nt][i] = 0.f;

    auto prefetch = [&](int it, int st) {
        const int k0 = it * GBK;
        const uint32_t aoff = smem_base + (uint32_t)(st * A_STAGE) * 2u;
        const uint32_t boff = smem_base + (uint32_t)((2 * A_STAGE + st * B_STAGE)) * 2u;
#pragma unroll
        for (int c = 0; c < 4; c++) {
            int i = t + 256 * c;
            int row = i >> 3, c8 = i & 7;
            int gr = m0 + row;
            uint32_t dst = aoff + (uint32_t)(row * SSTR + c8 * 8) * 2u;
            const void* src = &g_Tb[(size_t)(gr < NN ? gr : 0) * KK + k0 + c8 * 8];
            cp16(dst, src, (gr < NN) ? 16u : 0u);
        }
#pragma unroll
        for (int c = 0; c < 4; c++) {
            int i = t + 256 * c;
            int row = i >> 3, c8 = i & 7;
            uint32_t dst = boff + (uint32_t)(row * SSTR + c8 * 8) * 2u;
            cp16(dst, &g_wt[(size_t)row * KK + k0 + c8 * 8], 16u);
        }
        asm volatile("cp.async.commit_group;\n" ::: "memory");
    };

    prefetch(0, 0);

    for (int it = 0; it < NIT; it++) {
        const int cur = it & 1;
        if (it + 1 < NIT) prefetch(it + 1, cur ^ 1);
        if (it + 1 < NIT)
            asm volatile("cp.async.wait_group 1;\n" ::: "memory");
        else
            asm volatile("cp.async.wait_group 0;\n" ::: "memory");
        __syncthreads();

        const __nv_bfloat16* As = smem + cur * A_STAGE;
        const __nv_bfloat16* Bs = smem + 2 * A_STAGE + cur * B_STAGE;

#pragma unroll
        for (int ks = 0; ks < GBK; ks += 16) {
            uint32_t af[2][4];
#pragma unroll
            for (int mt = 0; mt < 2; mt++) {
                int rb = R0 + mt * 16;
                af[mt][0] = *(const uint32_t*)&As[(rb + g) * SSTR + ks + 2 * tig];
                af[mt][1] = *(const uint32_t*)&As[(rb + g + 8) * SSTR + ks + 2 * tig];
                af[mt][2] = *(const uint32_t*)&As[(rb + g) * SSTR + ks + 8 + 2 * tig];
                af[mt][3] = *(const uint32_t*)&As[(rb + g + 8) * SSTR + ks + 8 + 2 * tig];
            }
#pragma unroll
            for (int nt = 0; nt < 8; nt++) {
                int cb = C0 + nt * 8 + g;
                uint32_t b0 = *(const uint32_t*)&Bs[cb * SSTR + ks + 2 * tig];
                uint32_t b1 = *(const uint32_t*)&Bs[cb * SSTR + ks + 8 + 2 * tig];
#pragma unroll
                for (int mt = 0; mt < 2; mt++) {
                    asm volatile(
                        "mma.sync.aligned.m16n8k16.row.col.f32.bf16.bf16.f32 "
                        "{%0,%1,%2,%3}, {%4,%5,%6,%7}, {%8,%9}, {%0,%1,%2,%3};"
                        : "+f"(acc[mt][nt][0]), "+f"(acc[mt][nt][1]),
                          "+f"(acc[mt][nt][2]), "+f"(acc[mt][nt][3])
                        : "r"(af[mt][0]), "r"(af[mt][1]), "r"(af[mt][2]), "r"(af[mt][3]),
                          "r"(b0), "r"(b1));
                }
            }
        }
        __syncthreads();
    }

#pragma unroll
    for (int mt = 0; mt < 2; mt++) {
        int row0 = m0 + R0 + mt * 16 + g;
        int row1 = row0 + 8;
#pragma unroll
        for (int nt = 0; nt < 8; nt++) {
            int col = C0 + nt * 8 + 2 * tig;
            float2 b = *(const float2*)&bias[col];
            if (row0 < NN) {
                const float2 xr = *(const float2*)&x[(size_t)row0 * DD + col];
                float2 o;
                o.x = acc[mt][nt][0] + b.x + xr.x;
                o.y = acc[mt][nt][1] + b.y + xr.y;
                *(float2*)&out[(size_t)row0 * DD + col] = o;
            }
            if (row1 < NN) {
                const float2 xr = *(const float2*)&x[(size_t)row1 * DD + col];
                float2 o;
                o.x = acc[mt][nt][2] + b.x + xr.x;
                o.y = acc[mt][nt][3] + b.y + xr.y;
                *(float2*)&out[(size_t)row1 * DD + col] = o;
            }
        }
    }
}

// ---------------- launch ----------------
extern "C" void kernel_launch(void* const* d_in, const int* in_sizes, int n_in,
                              void* d_out, int out_size)
{
    const float* x     = (const float*)d_in[0];
    const int*   ei    = (const int*)  d_in[1];
    const int*   etype = (const int*)  d_in[2];
    const float* w     = (const float*)d_in[3];
    const float* qv    = (const float*)d_in[4];
    const float* kv    = (const float*)d_in[5];
    const float* bias  = (const float*)d_in[6];

    float* out       = (float*)d_out;
    float* alpha_out = out + (size_t)NN * DD;

    setup_kernel<<<ZB + 192, 256>>>(w, qv, kv);                   // #1
    scatter_kernel<<<(EE + 255) / 256, 256>>>(ei, etype);         // #2
    nqnk_kernel<<<(NN * 32 + 255) / 256, 256>>>(x);               // #3
    node_kernel<<<(NN * 32 + 255) / 256, 256>>>(alpha_out);       // #4  <- profiled
    cudaFuncSetAttribute(gemm_tc_kernel,
                         cudaFuncAttributeMaxDynamicSharedMemorySize, SMEM_ELEMS * 2);
    gemm_tc_kernel<<<(NN + GBM - 1) / GBM, 256, SMEM_ELEMS * 2>>>(x, bias, out); // #5
}